// round 16
// baseline (speedup 1.0000x reference)
#include <cuda_runtime.h>
#include <cuda_fp16.h>
#include <cstdint>
#include <cstddef>

// ---------------- problem constants ----------------
#define BATCH 4
#define CDIM  256
#define CIDIM 128
#define NDIM  4096
#define SQRT_LOG2E 1.2011224087864498f

// ---------------- scratch (device globals) ----------------
__device__ __half g_xT_h[BATCH * NDIM * CDIM];     // x^T [b][n][c] hi
__device__ __half g_xT_l[BATCH * NDIM * CDIM];
__device__ __half g_W_h[3 * CIDIM * CDIM];         // theta/phi/g weights stacked
__device__ __half g_W_l[3 * CIDIM * CDIM];
__device__ __half g_OW[CDIM * CIDIM];              // out_w single fp16
__device__ __half g_thph_h[BATCH * NDIM * 256];    // [b][n][0:128]=theta, [128:256]=phi (x sqrt(log2 e))
__device__ __half g_thph_l[BATCH * NDIM * 256];
__device__ __half g_gv[BATCH * CIDIM * NDIM];      // g [b][ci][m], single fp16

// ---------------- helpers ----------------
__device__ __forceinline__ uint32_t smem_u32(const void* p) {
    uint32_t a;
    asm("{ .reg .u64 t; cvta.to.shared.u64 t, %1; cvt.u32.u64 %0, t; }" : "=r"(a) : "l"(p));
    return a;
}
__device__ __forceinline__ void cp16(uint32_t s, const void* g) {
    asm volatile("cp.async.cg.shared.global [%0], [%1], 16;" :: "r"(s), "l"(g));
}
#define CP_COMMIT() asm volatile("cp.async.commit_group;" ::: "memory")

#define LDSM_X4(r, addr) \
    asm volatile("ldmatrix.sync.aligned.m8n8.x4.shared.b16 {%0,%1,%2,%3}, [%4];" \
        : "=r"((r)[0]), "=r"((r)[1]), "=r"((r)[2]), "=r"((r)[3]) : "r"(addr))

#define MMAF16(d, a, b0, b1) \
    asm volatile("mma.sync.aligned.m16n8k16.row.col.f32.f16.f16.f32 " \
        "{%0,%1,%2,%3}, {%4,%5,%6,%7}, {%8,%9}, {%0,%1,%2,%3};" \
        : "+f"((d)[0]), "+f"((d)[1]), "+f"((d)[2]), "+f"((d)[3]) \
        : "r"((a)[0]), "r"((a)[1]), "r"((a)[2]), "r"((a)[3]), "r"(b0), "r"(b1))

__device__ __forceinline__ void split_f16(float v, __half& h, __half& l) {
    h = __float2half_rn(v);
    l = __float2half_rn(v - __half2float(h));
}
__device__ __forceinline__ float ex2(float x) {
    float y;
    asm("ex2.approx.f32 %0, %1;" : "=f"(y) : "f"(x));
    return y;
}
__device__ __forceinline__ uint32_t swz(uint32_t off) { return off ^ ((off >> 3) & 0x70); }

// ---------------- merged projection kernel (theta|phi AND g in one launch) ----------------
__global__ __launch_bounds__(256, 2)
void proj_k(const __half* __restrict__ xTh, const __half* __restrict__ xTl,
            const __half* __restrict__ Wh, const __half* __restrict__ Wl,
            const float* __restrict__ theta_b, const float* __restrict__ phi_b,
            const float* __restrict__ g_b,
            __half* __restrict__ tpH, __half* __restrict__ tpL,
            __half* __restrict__ gv)
{
    extern __shared__ char dsm[];
    const uint32_t smem = (smem_u32(dsm) + 1023u) & ~1023u;
    const int STG = 32768;

    const int tid  = threadIdx.x;
    const int wid  = tid >> 5;
    const int lane = tid & 31;
    const int wm   = wid >> 2;
    const int wn   = wid & 3;

    const int gx = blockIdx.x;
    const int by = blockIdx.y;
    const int bz = blockIdx.z;
    const size_t sXT = (size_t)NDIM * CDIM;
    const size_t sTP = (size_t)NDIM * 256;
    const size_t sG  = (size_t)CIDIM * NDIM;

    const __half *Ah, *Al, *Bh, *Bl;
    int am0, bn0;
    if (gx < 2) {
        Ah = xTh + bz * sXT;  Al = xTl + bz * sXT;
        Bh = Wh + gx * 32768; Bl = Wl + gx * 32768;
        am0 = by * 128; bn0 = 0;
    } else {
        Ah = Wh + 65536;      Al = Wl + 65536;
        Bh = xTh + bz * sXT;  Bl = xTl + bz * sXT;
        am0 = 0; bn0 = by * 128;
    }

    const int lrow = tid >> 3;
    const int lc16 = tid & 7;

    float acc[4][4][4];
#pragma unroll
    for (int i = 0; i < 4; i++)
#pragma unroll
        for (int j = 0; j < 4; j++)
#pragma unroll
            for (int r = 0; r < 4; r++) acc[i][j][r] = 0.f;

    auto load_chunk = [&](int c) {
        const int p  = c >> 2;
        const int k0 = (c & 3) * 64;
        const __half* Aop = (p < 2) ? Ah : Al;
        const __half* Bop = (p == 1) ? Bl : Bh;
        const uint32_t sb = smem + (c & 1) * STG;
#pragma unroll
        for (int it = 0; it < 4; it++) {
            int row = lrow + it * 32;
            uint32_t off = swz(row * 128 + lc16 * 16);
            cp16(sb + off, Aop + (size_t)(am0 + row) * CDIM + k0 + lc16 * 8);
        }
#pragma unroll
        for (int it = 0; it < 4; it++) {
            int row = lrow + it * 32;
            uint32_t off = swz(row * 128 + lc16 * 16);
            cp16(sb + 16384 + off, Bop + (size_t)(bn0 + row) * CDIM + k0 + lc16 * 8);
        }
        CP_COMMIT();
    };

    const int rA  = wm * 64 + (lane & 15);
    const int cA  = lane >> 4;
    const int rB  = wn * 32 + (lane & 7) + ((lane >> 4) << 3);
    const int cB  = (lane >> 3) & 1;

    load_chunk(0);
    for (int c = 0; c < 12; c++) {
        if (c + 1 < 12) {
            load_chunk(c + 1);
            asm volatile("cp.async.wait_group 1;" ::: "memory");
        } else {
            asm volatile("cp.async.wait_group 0;" ::: "memory");
        }
        __syncthreads();
        const uint32_t sAb = smem + (c & 1) * STG;
        const uint32_t sBb = sAb + 16384;
#pragma unroll
        for (int k16 = 0; k16 < 4; k16++) {
            uint32_t a[4][4];
#pragma unroll
            for (int mi = 0; mi < 4; mi++) {
                uint32_t off = swz((rA + mi * 16) * 128 + (k16 * 2 + cA) * 16);
                LDSM_X4(a[mi], sAb + off);
            }
            uint32_t bf[2][4];
#pragma unroll
            for (int njp = 0; njp < 2; njp++) {
                uint32_t off = swz((rB + njp * 16) * 128 + (k16 * 2 + cB) * 16);
                LDSM_X4(bf[njp], sBb + off);
            }
#pragma unroll
            for (int mi = 0; mi < 4; mi++)
#pragma unroll
                for (int nj = 0; nj < 4; nj++)
                    MMAF16(acc[mi][nj], a[mi], bf[nj >> 1][(nj & 1) * 2], bf[nj >> 1][(nj & 1) * 2 + 1]);
        }
        __syncthreads();
    }

    const int mb = am0 + wm * 64 + (lane >> 2);
    const int nb = wn * 32 + (lane & 3) * 2;
    if (gx < 2) {
        const float* bp = (gx == 0) ? theta_b : phi_b;
#pragma unroll
        for (int mi = 0; mi < 4; mi++) {
#pragma unroll
            for (int half = 0; half < 2; half++) {
                const int m = mb + mi * 16 + half * 8;
#pragma unroll
                for (int nj = 0; nj < 4; nj++) {
                    const int n = nb + nj * 8;
                    float v0 = (acc[mi][nj][half * 2 + 0] + bp[n])     * SQRT_LOG2E;
                    float v1 = (acc[mi][nj][half * 2 + 1] + bp[n + 1]) * SQRT_LOG2E;
                    __half h0, l0, h1, l1;
                    split_f16(v0, h0, l0);
                    split_f16(v1, h1, l1);
                    __half2 hh; hh.x = h0; hh.y = h1;
                    __half2 ll; ll.x = l0; ll.y = l1;
                    const size_t addr = bz * sTP + (size_t)m * 256 + gx * 128 + n;
                    *(__half2*)&tpH[addr] = hh;
                    *(__half2*)&tpL[addr] = ll;
                }
            }
        }
    } else {
#pragma unroll
        for (int mi = 0; mi < 4; mi++) {
#pragma unroll
            for (int half = 0; half < 2; half++) {
                const int m = mb + mi * 16 + half * 8;
                const float bv = g_b[m];
#pragma unroll
                for (int nj = 0; nj < 4; nj++) {
                    const int n = by * 128 + nb + nj * 8;
                    __half2 hh;
                    hh.x = __float2half_rn(acc[mi][nj][half * 2 + 0] + bv);
                    hh.y = __float2half_rn(acc[mi][nj][half * 2 + 1] + bv);
                    *(__half2*)&gv[bz * sG + (size_t)m * NDIM + n] = hh;
                }
            }
        }
    }
}

// ---------------- fused attention + final projection: 512 threads, col-split flash ----------------
// Grid (32 n-tiles, BATCH), 16 warps. Warp (wr=wid&7, wc=wid>>3):
//   rows wr*16..+16, S columns wc*64..+64 (independent flash recurrence per warp),
//   O partial = P_half . g (full 128 ci, half m). Epilogue merges partner partials
//   (split-flash combine), then in-block final projection.
__global__ __launch_bounds__(512, 1)
void fused_attn(const __half* __restrict__ thph_h, const __half* __restrict__ thph_l,
                const __half* __restrict__ gv,
                const __half* __restrict__ OW,
                const float* __restrict__ out_b,
                const float* __restrict__ x,
                float* __restrict__ out)
{
    extern __shared__ char dsm[];
    const uint32_t smem = (smem_u32(dsm) + 1023u) & ~1023u;
    const uint32_t THH = smem + 5u * 32768u;   // theta hi persistent
    const uint32_t THL = smem + 6u * 32768u;   // theta lo persistent
    __shared__ float mxb[16][16];
    __shared__ float rsb[16][16];

    const int tid = threadIdx.x, wid = tid >> 5, lane = tid & 31;
    const int wr = wid & 7, wc = wid >> 3;
    const int b = blockIdx.y, n0 = blockIdx.x * 128;
    const size_t sTP = (size_t)NDIM * 256, sG = (size_t)CIDIM * NDIM;
    const size_t sX = (size_t)CDIM * NDIM;
    const __half* thH = thph_h + (size_t)b * sTP + (size_t)n0 * 256;
    const __half* thL = thph_l + (size_t)b * sTP + (size_t)n0 * 256;
    const __half* phH = thph_h + (size_t)b * sTP + 128;
    const __half* phL = thph_l + (size_t)b * sTP + 128;
    const __half* gvb = gv + (size_t)b * sG;

    auto load_tile = [&](uint32_t dst, const __half* base, int rowStride) {
#pragma unroll
        for (int it = 0; it < 4; it++) {
            int idx = tid + it * 512;
            int sub = idx >> 10, r = (idx >> 3) & 127, c16 = idx & 7;
            cp16(dst + sub * 16384 + swz(r * 128 + c16 * 16),
                 base + (size_t)r * rowStride + sub * 64 + c16 * 8);
        }
        CP_COMMIT();
    };
    // items: iter t -> {3t: phiH(t), 3t+1: phiL(t), 3t+2: g(t)}, slot = i % 5
    auto issue_item = [&](int i) {
        const int t = i / 3, j = i - 3 * t;
        const uint32_t dst = smem + (uint32_t)(i % 5) * 32768u;
        if (j == 0)      load_tile(dst, phH + (size_t)t * 128 * 256, 256);
        else if (j == 1) load_tile(dst, phL + (size_t)t * 128 * 256, 256);
        else             load_tile(dst, gvb + t * 128, NDIM);
    };

    // prologue: 7 groups
    load_tile(THH, thH, 256);
    load_tile(THL, thL, 256);
    issue_item(0); issue_item(1); issue_item(2); issue_item(3); issue_item(4);

    // fragment addressing
    const uint32_t aOff  = (uint32_t)((wr * 16 + (lane & 15)) * 128 + (lane >> 4) * 16);
    const uint32_t bOffS = (uint32_t)(((wc * 64 + (lane & 7) + ((lane >> 4) << 3)) * 128) + ((lane >> 3) & 1) * 16);
    const uint32_t bOffG = (uint32_t)((((lane & 7) + ((lane >> 4) << 3)) * 128) + ((lane >> 3) & 1) * 16);

    float S[8][4];
    float O[16][4];
#pragma unroll
    for (int nj = 0; nj < 16; nj++) { O[nj][0] = O[nj][1] = O[nj][2] = O[nj][3] = 0.f; }
    float rs0 = 0.f, rs1 = 0.f, mx0 = -1e30f, mx1 = -1e30f;

    for (int t = 0; t < 32; t++) {
#pragma unroll
        for (int nj = 0; nj < 8; nj++) { S[nj][0] = S[nj][1] = S[nj][2] = S[nj][3] = 0.f; }
        uint32_t* Sp = reinterpret_cast<uint32_t*>(&S[0][0]);
        const int i0 = 3 * t;

        // ---- stage 0 (phiH): S += thH*phiH + thL*phiH
        asm volatile("cp.async.wait_group 4;" ::: "memory");
        __syncthreads();
        {
            const uint32_t B0 = smem + (uint32_t)(i0 % 5) * 32768u;
#pragma unroll
            for (int q = 0; q < 8; q++) {
                const uint32_t so = (uint32_t)(q >> 2) * 16384, ko = (uint32_t)(q & 3) * 32;
                uint32_t tH[4], tL[4];
                LDSM_X4(tH, THH + so + swz(aOff + ko));
                LDSM_X4(tL, THL + so + swz(aOff + ko));
#pragma unroll
                for (int p = 0; p < 4; p++) {
                    uint32_t bb[4];
                    LDSM_X4(bb, B0 + so + swz(bOffS + (uint32_t)p * 2048 + ko));
                    MMAF16(S[2 * p],     tH, bb[0], bb[1]);
                    MMAF16(S[2 * p + 1], tH, bb[2], bb[3]);
                    MMAF16(S[2 * p],     tL, bb[0], bb[1]);
                    MMAF16(S[2 * p + 1], tL, bb[2], bb[3]);
                }
            }
        }
        __syncthreads();
        if (i0 + 5 < 96) issue_item(i0 + 5); else CP_COMMIT();

        // ---- stage 1 (phiL): S += thH*phiL
        asm volatile("cp.async.wait_group 4;" ::: "memory");
        __syncthreads();
        {
            const uint32_t B1 = smem + (uint32_t)((i0 + 1) % 5) * 32768u;
#pragma unroll
            for (int q = 0; q < 8; q++) {
                const uint32_t so = (uint32_t)(q >> 2) * 16384, ko = (uint32_t)(q & 3) * 32;
                uint32_t tH[4];
                LDSM_X4(tH, THH + so + swz(aOff + ko));
#pragma unroll
                for (int p = 0; p < 4; p++) {
                    uint32_t bb[4];
                    LDSM_X4(bb, B1 + so + swz(bOffS + (uint32_t)p * 2048 + ko));
                    MMAF16(S[2 * p],     tH, bb[0], bb[1]);
                    MMAF16(S[2 * p + 1], tH, bb[2], bb[3]);
                }
            }
        }
        __syncthreads();
        if (i0 + 6 < 96) issue_item(i0 + 6); else CP_COMMIT();

        // ---- convert: per-warp local flash (no cross-warp sync)
        float cm0 = -1e30f, cm1 = -1e30f;
#pragma unroll
        for (int nj = 0; nj < 8; nj++) {
            cm0 = fmaxf(cm0, fmaxf(S[nj][0], S[nj][1]));
            cm1 = fmaxf(cm1, fmaxf(S[nj][2], S[nj][3]));
        }
        cm0 = fmaxf(cm0, __shfl_xor_sync(0xFFFFFFFFu, cm0, 1));
        cm0 = fmaxf(cm0, __shfl_xor_sync(0xFFFFFFFFu, cm0, 2));
        cm1 = fmaxf(cm1, __shfl_xor_sync(0xFFFFFFFFu, cm1, 1));
        cm1 = fmaxf(cm1, __shfl_xor_sync(0xFFFFFFFFu, cm1, 2));
        const float nm0 = fmaxf(mx0, cm0), nm1 = fmaxf(mx1, cm1);
        const float f0 = ex2(mx0 - nm0), f1 = ex2(mx1 - nm1);
        mx0 = nm0; mx1 = nm1;
        rs0 *= f0; rs1 *= f1;
#pragma unroll
        for (int nj = 0; nj < 16; nj++) {
            O[nj][0] *= f0; O[nj][1] *= f0; O[nj][2] *= f1; O[nj][3] *= f1;
        }
#pragma unroll
        for (int nj = 0; nj < 8; nj++) {
            float e0 = ex2(S[nj][0] - mx0), e1 = ex2(S[nj][1] - mx0);
            float e2 = ex2(S[nj][2] - mx1), e3 = ex2(S[nj][3] - mx1);
            rs0 += e0 + e1; rs1 += e2 + e3;
            __half2 p0 = __floats2half2_rn(e0, e1);
            __half2 p1 = __floats2half2_rn(e2, e3);
            Sp[2 * nj]     = *(uint32_t*)&p0;
            Sp[2 * nj + 1] = *(uint32_t*)&p1;
        }

        // ---- stage 2 (g): O += P_half * g  (k = warp's 64 m-cols, full 128 ci)
        asm volatile("cp.async.wait_group 4;" ::: "memory");
        __syncthreads();
        {
            const uint32_t B2 = smem + (uint32_t)((i0 + 2) % 5) * 32768u + (uint32_t)wc * 16384u;
#pragma unroll
            for (int q = 0; q < 4; q++) {
                const uint32_t ko = (uint32_t)q * 32;
                uint32_t aP[4] = { Sp[4 * q], Sp[4 * q + 1], Sp[4 * q + 2], Sp[4 * q + 3] };
#pragma unroll
                for (int p = 0; p < 8; p++) {
                    uint32_t bb[4];
                    LDSM_X4(bb, B2 + swz(bOffG + (uint32_t)p * 2048 + ko));
                    MMAF16(O[2 * p],     aP, bb[0], bb[1]);
                    MMAF16(O[2 * p + 1], aP, bb[2], bb[3]);
                }
            }
        }
        __syncthreads();
        if (i0 + 7 < 96) issue_item(i0 + 7); else CP_COMMIT();
    }

    // ================= split-flash merge + final projection =================
    // per-row sums within warp half
    rs0 += __shfl_xor_sync(0xFFFFFFFFu, rs0, 1);
    rs0 += __shfl_xor_sync(0xFFFFFFFFu, rs0, 2);
    rs1 += __shfl_xor_sync(0xFFFFFFFFu, rs1, 1);
    rs1 += __shfl_xor_sync(0xFFFFFFFFu, rs1, 2);
    {
        const int r = lane >> 2;
        if ((lane & 3) == 0) {
            mxb[wid][r] = mx0; mxb[wid][r + 8] = mx1;
            rsb[wid][r] = rs0; rsb[wid][r + 8] = rs1;
        }
    }
    __syncthreads();
    float s0, s1;
    {
        const int r = lane >> 2;
        const int pw = wid ^ 8;
        const float pm0 = mxb[pw][r], pm1 = mxb[pw][r + 8];
        const float pr0 = rsb[pw][r], pr1 = rsb[pw][r + 8];
        const float mg0 = fmaxf(mx0, pm0), mg1 = fmaxf(mx1, pm1);
        const float f0 = ex2(mx0 - mg0), f1 = ex2(mx1 - mg1);
        const float inv0 = 1.f / (rs0 * f0 + pr0 * ex2(pm0 - mg0));
        const float inv1 = 1.f / (rs1 * f1 + pr1 * ex2(pm1 - mg1));
        s0 = f0 * inv0; s1 = f1 * inv1;
    }

    // prefetch OW into slots 0,1
    load_tile(smem + 0u,     OW, CIDIM);
    load_tile(smem + 32768u, OW + 128 * CIDIM, CIDIM);

    // combine O partials into mid tile (slot 2), fp16 [n 128][ci 128]
    char* dbase = (char*)(((uintptr_t)dsm + 1023u) & ~(uintptr_t)1023u);
    char* MIDp = dbase + 2u * 32768u;
    const int rloc = wr * 16 + (lane >> 2);
    if (wc == 0) {
#pragma unroll
        for (int nj = 0; nj < 16; nj++) {
            const int col = nj * 8 + (lane & 3) * 2;
            const uint32_t sub = (uint32_t)(col >> 6) * 16384u;
            const uint32_t cb  = (uint32_t)(col & 63) * 2u;
            __half2 v0 = __floats2half2_rn(O[nj][0] * s0, O[nj][1] * s0);
            __half2 v1 = __floats2half2_rn(O[nj][2] * s1, O[nj][3] * s1);
            *(__half2*)(MIDp + sub + swz((uint32_t)rloc * 128u + cb))       = v0;
            *(__half2*)(MIDp + sub + swz((uint32_t)(rloc + 8) * 128u + cb)) = v1;
        }
    }
    __syncthreads();
    if (wc == 1) {
#pragma unroll
        for (int nj = 0; nj < 16; nj++) {
            const int col = nj * 8 + (lane & 3) * 2;
            const uint32_t sub = (uint32_t)(col >> 6) * 16384u;
            const uint32_t cb  = (uint32_t)(col & 63) * 2u;
            char* a0 = MIDp + sub + swz((uint32_t)rloc * 128u + cb);
            char* a1 = MIDp + sub + swz((uint32_t)(rloc + 8) * 128u + cb);
            float2 u0 = __half22float2(*(__half2*)a0);
            float2 u1 = __half22float2(*(__half2*)a1);
            *(__half2*)a0 = __floats2half2_rn(u0.x + O[nj][0] * s0, u0.y + O[nj][1] * s0);
            *(__half2*)a1 = __floats2half2_rn(u1.x + O[nj][2] * s1, u1.y + O[nj][3] * s1);
        }
    }
    asm volatile("cp.async.wait_group 0;" ::: "memory");
    __syncthreads();

    // final mini-GEMM: out[c][n] = OW[c,:].mid[n,:]  (16 warps: 4 c-groups x 4 n-groups)
    const int wm2 = wid >> 2;          // c-group of 64
    const int wn2 = wid & 3;           // n-group of 32
    const uint32_t aOff2 = (uint32_t)(((wm2 & 1) * 64 + (lane & 15)) * 128 + (lane >> 4) * 16);
    const uint32_t bOff2 = (uint32_t)(((wn2 * 32 + (lane & 7) + ((lane >> 4) << 3)) * 128) + ((lane >> 3) & 1) * 16);
    const uint32_t OWb = smem + (uint32_t)(wm2 >> 1) * 32768u;
    const uint32_t MID = smem + 2u * 32768u;

    float acc[4][4][4];
#pragma unroll
    for (int i = 0; i < 4; i++)
#pragma unroll
        for (int j = 0; j < 4; j++)
#pragma unroll
            for (int r = 0; r < 4; r++) acc[i][j][r] = 0.f;
#pragma unroll
    for (int q = 0; q < 8; q++) {
        const uint32_t so = (uint32_t)(q >> 2) * 16384, ko = (uint32_t)(q & 3) * 32;
        uint32_t a[4][4];
#pragma unroll
        for (int mi = 0; mi < 4; mi++)
            LDSM_X4(a[mi], OWb + so + swz(aOff2 + (uint32_t)mi * 2048u + ko));
        uint32_t bf[2][4];
#pragma unroll
        for (int njp = 0; njp < 2; njp++)
            LDSM_X4(bf[njp], MID + so + swz(bOff2 + (uint32_t)njp * 2048u + ko));
#pragma unroll
        for (int mi = 0; mi < 4; mi++)
#pragma unroll
            for (int nj = 0; nj < 4; nj++)
                MMAF16(acc[mi][nj], a[mi], bf[nj >> 1][(nj & 1) * 2], bf[nj >> 1][(nj & 1) * 2 + 1]);
    }
    const int cb0 = wm2 * 64 + (lane >> 2);
    const int nb2 = n0 + wn2 * 32 + (lane & 3) * 2;
#pragma unroll
    for (int mi = 0; mi < 4; mi++) {
#pragma unroll
        for (int half = 0; half < 2; half++) {
            const int c = cb0 + mi * 16 + half * 8;
            const float bv = out_b[c];
#pragma unroll
            for (int nj = 0; nj < 4; nj++) {
                const int n = nb2 + nj * 8;
                const size_t addr = (size_t)b * sX + (size_t)c * NDIM + n;
                float2 xv = *(const float2*)&x[addr];
                float2 f;
                f.x = acc[mi][nj][half * 2 + 0] + bv + xv.x;
                f.y = acc[mi][nj][half * 2 + 1] + bv + xv.y;
                *(float2*)&out[addr] = f;
            }
        }
    }
}

// ---------------- prep kernels ----------------
__global__ void split4_k(const float* __restrict__ tw, const float* __restrict__ pw,
                         const float* __restrict__ gw, const float* __restrict__ ow,
                         __half* __restrict__ Wh, __half* __restrict__ Wl,
                         __half* __restrict__ OWs)
{
    const int i = blockIdx.x * 256 + threadIdx.x;
    const int seg = i >> 15, loc = i & 32767;
    if (seg < 3) {
        const float* s = (seg == 0) ? tw : (seg == 1) ? pw : gw;
        __half hh, ll;
        split_f16(s[loc], hh, ll);
        Wh[seg * 32768 + loc] = hh;
        Wl[seg * 32768 + loc] = ll;
    } else {
        OWs[loc] = __float2half_rn(ow[loc]);
    }
}

__global__ void xT_split_k(const float* __restrict__ x,
                           __half* __restrict__ th, __half* __restrict__ tl)
{
    __shared__ float t[32][33];
    const int b = blockIdx.z;
    const int n0 = blockIdx.x * 32, c0 = blockIdx.y * 32;
    const int tx = threadIdx.x, ty = threadIdx.y;
    const float* xb = x + (size_t)b * CDIM * NDIM;
#pragma unroll
    for (int i = 0; i < 32; i += 8)
        t[ty + i][tx] = xb[(size_t)(c0 + ty + i) * NDIM + n0 + tx];
    __syncthreads();
    __half* oh = th + (size_t)b * NDIM * CDIM;
    __half* ol = tl + (size_t)b * NDIM * CDIM;
#pragma unroll
    for (int i = 0; i < 32; i += 8) {
        __half h, l;
        split_f16(t[tx][ty + i], h, l);
        size_t a = (size_t)(n0 + ty + i) * CDIM + c0 + tx;
        oh[a] = h; ol[a] = l;
    }
}

// ---------------- launch ----------------
extern "C" void kernel_launch(void* const* d_in, const int* in_sizes, int n_in,
                              void* d_out, int out_size)
{
    const float* x       = (const float*)d_in[0];
    const float* theta_w = (const float*)d_in[1];
    const float* theta_b = (const float*)d_in[2];
    const float* phi_w   = (const float*)d_in[3];
    const float* phi_b   = (const float*)d_in[4];
    const float* g_w     = (const float*)d_in[5];
    const float* g_b     = (const float*)d_in[6];
    const float* out_w   = (const float*)d_in[7];
    const float* out_b   = (const float*)d_in[8];
    float* out = (float*)d_out;

    __half *xTh, *xTl, *Wh, *Wl, *OWs, *tpH, *tpL, *gv;
    cudaGetSymbolAddress((void**)&xTh, g_xT_h);   cudaGetSymbolAddress((void**)&xTl, g_xT_l);
    cudaGetSymbolAddress((void**)&Wh,  g_W_h);    cudaGetSymbolAddress((void**)&Wl,  g_W_l);
    cudaGetSymbolAddress((void**)&OWs, g_OW);
    cudaGetSymbolAddress((void**)&tpH, g_thph_h); cudaGetSymbolAddress((void**)&tpL, g_thph_l);
    cudaGetSymbolAddress((void**)&gv,  g_gv);

    const int SM  = 1024 + 2 * 32768;      // proj_k: 66560
    const int SMF = 1024 + 7 * 32768;      // fused: 5-slot ring + thetaH + thetaL = 230400
    cudaFuncSetAttribute(proj_k, cudaFuncAttributeMaxDynamicSharedMemorySize, SM);
    cudaFuncSetAttribute(fused_attn, cudaFuncAttributeMaxDynamicSharedMemorySize, SMF);

    // prep
    split4_k<<<512, 256>>>(theta_w, phi_w, g_w, out_w, Wh, Wl, OWs);
    xT_split_k<<<dim3(NDIM / 32, CDIM / 32, BATCH), dim3(32, 8)>>>(x, xTh, xTl);

    // 1) merged projections: theta|phi (x=0,1) and g (x=2)
    proj_k<<<dim3(3, 32, BATCH), 256, SM>>>(
        xTh, xTl, Wh, Wl, theta_b, phi_b, g_b, tpH, tpL, gv);

    // 2) fused attention + final projection -> out
    fused_attn<<<dim3(NDIM / 128, BATCH), 512, SMF>>>(
        tpH, tpL, gv, OWs, out_b, x, out);
}

// round 17
// speedup vs baseline: 1.4070x; 1.4070x over previous
#include <cuda_runtime.h>
#include <cuda_fp16.h>
#include <cstdint>
#include <cstddef>

// ---------------- problem constants ----------------
#define BATCH 4
#define CDIM  256
#define CIDIM 128
#define NDIM  4096
#define SQRT_LOG2E 1.2011224087864498f

// ---------------- scratch (device globals) ----------------
__device__ __half g_xT_h[BATCH * NDIM * CDIM];     // x^T [b][n][c] hi
__device__ __half g_xT_l[BATCH * NDIM * CDIM];
__device__ __half g_W_h[3 * CIDIM * CDIM];         // theta/phi/g weights stacked
__device__ __half g_W_l[3 * CIDIM * CDIM];
__device__ __half g_OW[CDIM * CIDIM];              // out_w single fp16
__device__ __half g_thph_h[BATCH * NDIM * 256];    // [b][n][0:128]=theta, [128:256]=phi (x sqrt(log2 e))
__device__ __half g_thph_l[BATCH * NDIM * 256];
__device__ __half g_gv[BATCH * CIDIM * NDIM];      // g [b][ci][m], single fp16

// ---------------- helpers ----------------
__device__ __forceinline__ uint32_t smem_u32(const void* p) {
    uint32_t a;
    asm("{ .reg .u64 t; cvta.to.shared.u64 t, %1; cvt.u32.u64 %0, t; }" : "=r"(a) : "l"(p));
    return a;
}
__device__ __forceinline__ void cp16(uint32_t s, const void* g) {
    asm volatile("cp.async.cg.shared.global [%0], [%1], 16;" :: "r"(s), "l"(g));
}
#define CP_COMMIT() asm volatile("cp.async.commit_group;" ::: "memory")

#define LDSM_X4(r, addr) \
    asm volatile("ldmatrix.sync.aligned.m8n8.x4.shared.b16 {%0,%1,%2,%3}, [%4];" \
        : "=r"((r)[0]), "=r"((r)[1]), "=r"((r)[2]), "=r"((r)[3]) : "r"(addr))

#define MMAF16(d, a, b0, b1) \
    asm volatile("mma.sync.aligned.m16n8k16.row.col.f32.f16.f16.f32 " \
        "{%0,%1,%2,%3}, {%4,%5,%6,%7}, {%8,%9}, {%0,%1,%2,%3};" \
        : "+f"((d)[0]), "+f"((d)[1]), "+f"((d)[2]), "+f"((d)[3]) \
        : "r"((a)[0]), "r"((a)[1]), "r"((a)[2]), "r"((a)[3]), "r"(b0), "r"(b1))

__device__ __forceinline__ void split_f16(float v, __half& h, __half& l) {
    h = __float2half_rn(v);
    l = __float2half_rn(v - __half2float(h));
}
__device__ __forceinline__ float ex2(float x) {
    float y;
    asm("ex2.approx.f32 %0, %1;" : "=f"(y) : "f"(x));
    return y;
}
__device__ __forceinline__ uint32_t swz(uint32_t off) { return off ^ ((off >> 3) & 0x70); }

// ---------------- merged projection kernel (theta|phi AND g in one launch) ----------------
// grid (3, 32, BATCH). blockIdx.x: 0,1 -> theta|phi tile; 2 -> g tile.
__global__ __launch_bounds__(256, 2)
void proj_k(const __half* __restrict__ xTh, const __half* __restrict__ xTl,
            const __half* __restrict__ Wh, const __half* __restrict__ Wl,
            const float* __restrict__ theta_b, const float* __restrict__ phi_b,
            const float* __restrict__ g_b,
            __half* __restrict__ tpH, __half* __restrict__ tpL,
            __half* __restrict__ gv)
{
    extern __shared__ char dsm[];
    const uint32_t smem = (smem_u32(dsm) + 1023u) & ~1023u;
    const int STG = 32768;

    const int tid  = threadIdx.x;
    const int wid  = tid >> 5;
    const int lane = tid & 31;
    const int wm   = wid >> 2;
    const int wn   = wid & 3;

    const int gx = blockIdx.x;
    const int by = blockIdx.y;
    const int bz = blockIdx.z;
    const size_t sXT = (size_t)NDIM * CDIM;
    const size_t sTP = (size_t)NDIM * 256;
    const size_t sG  = (size_t)CIDIM * NDIM;

    const __half *Ah, *Al, *Bh, *Bl;
    int am0, bn0;
    if (gx < 2) {
        Ah = xTh + bz * sXT;  Al = xTl + bz * sXT;
        Bh = Wh + gx * 32768; Bl = Wl + gx * 32768;
        am0 = by * 128; bn0 = 0;
    } else {
        Ah = Wh + 65536;      Al = Wl + 65536;
        Bh = xTh + bz * sXT;  Bl = xTl + bz * sXT;
        am0 = 0; bn0 = by * 128;
    }

    const int lrow = tid >> 3;
    const int lc16 = tid & 7;

    float acc[4][4][4];
#pragma unroll
    for (int i = 0; i < 4; i++)
#pragma unroll
        for (int j = 0; j < 4; j++)
#pragma unroll
            for (int r = 0; r < 4; r++) acc[i][j][r] = 0.f;

    auto load_chunk = [&](int c) {
        const int p  = c >> 2;
        const int k0 = (c & 3) * 64;
        const __half* Aop = (p < 2) ? Ah : Al;
        const __half* Bop = (p == 1) ? Bl : Bh;
        const uint32_t sb = smem + (c & 1) * STG;
#pragma unroll
        for (int it = 0; it < 4; it++) {
            int row = lrow + it * 32;
            uint32_t off = swz(row * 128 + lc16 * 16);
            cp16(sb + off, Aop + (size_t)(am0 + row) * CDIM + k0 + lc16 * 8);
        }
#pragma unroll
        for (int it = 0; it < 4; it++) {
            int row = lrow + it * 32;
            uint32_t off = swz(row * 128 + lc16 * 16);
            cp16(sb + 16384 + off, Bop + (size_t)(bn0 + row) * CDIM + k0 + lc16 * 8);
        }
        CP_COMMIT();
    };

    const int rA  = wm * 64 + (lane & 15);
    const int cA  = lane >> 4;
    const int rB  = wn * 32 + (lane & 7) + ((lane >> 4) << 3);
    const int cB  = (lane >> 3) & 1;

    load_chunk(0);
    for (int c = 0; c < 12; c++) {
        if (c + 1 < 12) {
            load_chunk(c + 1);
            asm volatile("cp.async.wait_group 1;" ::: "memory");
        } else {
            asm volatile("cp.async.wait_group 0;" ::: "memory");
        }
        __syncthreads();
        const uint32_t sAb = smem + (c & 1) * STG;
        const uint32_t sBb = sAb + 16384;
#pragma unroll
        for (int k16 = 0; k16 < 4; k16++) {
            uint32_t a[4][4];
#pragma unroll
            for (int mi = 0; mi < 4; mi++) {
                uint32_t off = swz((rA + mi * 16) * 128 + (k16 * 2 + cA) * 16);
                LDSM_X4(a[mi], sAb + off);
            }
            uint32_t bf[2][4];
#pragma unroll
            for (int njp = 0; njp < 2; njp++) {
                uint32_t off = swz((rB + njp * 16) * 128 + (k16 * 2 + cB) * 16);
                LDSM_X4(bf[njp], sBb + off);
            }
#pragma unroll
            for (int mi = 0; mi < 4; mi++)
#pragma unroll
                for (int nj = 0; nj < 4; nj++)
                    MMAF16(acc[mi][nj], a[mi], bf[nj >> 1][(nj & 1) * 2], bf[nj >> 1][(nj & 1) * 2 + 1]);
        }
        __syncthreads();
    }

    const int mb = am0 + wm * 64 + (lane >> 2);
    const int nb = wn * 32 + (lane & 3) * 2;
    if (gx < 2) {
        const float* bp = (gx == 0) ? theta_b : phi_b;
#pragma unroll
        for (int mi = 0; mi < 4; mi++) {
#pragma unroll
            for (int half = 0; half < 2; half++) {
                const int m = mb + mi * 16 + half * 8;
#pragma unroll
                for (int nj = 0; nj < 4; nj++) {
                    const int n = nb + nj * 8;
                    float v0 = (acc[mi][nj][half * 2 + 0] + bp[n])     * SQRT_LOG2E;
                    float v1 = (acc[mi][nj][half * 2 + 1] + bp[n + 1]) * SQRT_LOG2E;
                    __half h0, l0, h1, l1;
                    split_f16(v0, h0, l0);
                    split_f16(v1, h1, l1);
                    __half2 hh; hh.x = h0; hh.y = h1;
                    __half2 ll; ll.x = l0; ll.y = l1;
                    const size_t addr = bz * sTP + (size_t)m * 256 + gx * 128 + n;
                    *(__half2*)&tpH[addr] = hh;
                    *(__half2*)&tpL[addr] = ll;
                }
            }
        }
    } else {
#pragma unroll
        for (int mi = 0; mi < 4; mi++) {
#pragma unroll
            for (int half = 0; half < 2; half++) {
                const int m = mb + mi * 16 + half * 8;
                const float bv = g_b[m];
#pragma unroll
                for (int nj = 0; nj < 4; nj++) {
                    const int n = by * 128 + nb + nj * 8;
                    __half2 hh;
                    hh.x = __float2half_rn(acc[mi][nj][half * 2 + 0] + bv);
                    hh.y = __float2half_rn(acc[mi][nj][half * 2 + 1] + bv);
                    *(__half2*)&gv[bz * sG + (size_t)m * NDIM + n] = hh;
                }
            }
        }
    }
}

// ---------------- fused attention + final projection (R13-proven shape) ----------------
// Grid (32 n-tiles, BATCH). 8 warps x (16 rows x 128 cols).
// S = 3 fp16 passes; P = 2^(S-mx) fp16; O += P*g. Then in-block final projection.
__global__ __launch_bounds__(256, 1)
void fused_attn(const __half* __restrict__ thph_h, const __half* __restrict__ thph_l,
                const __half* __restrict__ gv,
                const __half* __restrict__ OW,
                const float* __restrict__ out_b,
                const float* __restrict__ x,
                float* __restrict__ out)
{
    extern __shared__ char dsm[];
    const uint32_t smem = (smem_u32(dsm) + 1023u) & ~1023u;
    const uint32_t THL = smem + 5u * 32768u;   // thetaL staging

    const int tid = threadIdx.x, wid = tid >> 5, lane = tid & 31;
    const int b = blockIdx.y, n0 = blockIdx.x * 128;
    const size_t sTP = (size_t)NDIM * 256, sG = (size_t)CIDIM * NDIM;
    const size_t sX = (size_t)CDIM * NDIM;
    const __half* thH = thph_h + (size_t)b * sTP + (size_t)n0 * 256;
    const __half* thL = thph_l + (size_t)b * sTP + (size_t)n0 * 256;
    const __half* phH = thph_h + (size_t)b * sTP + 128;
    const __half* phL = thph_l + (size_t)b * sTP + 128;
    const __half* gvb = gv + (size_t)b * sG;

    auto load_tile = [&](uint32_t dst, const __half* base, int rowStride) {
#pragma unroll
        for (int it = 0; it < 8; it++) {
            int idx = tid + it * 256;
            int sub = idx >> 10, r = (idx >> 3) & 127, c16 = idx & 7;
            cp16(dst + sub * 16384 + swz(r * 128 + c16 * 16),
                 base + (size_t)r * rowStride + sub * 64 + c16 * 8);
        }
        CP_COMMIT();
    };
    // items: iter t -> {3t: phiH(t), 3t+1: phiL(t), 3t+2: g(t)}, slot = i % 5
    auto issue_item = [&](int i) {
        const int t = i / 3, j = i - 3 * t;
        const uint32_t dst = smem + (uint32_t)(i % 5) * 32768u;
        if (j == 0)      load_tile(dst, phH + (size_t)t * 128 * 256, 256);
        else if (j == 1) load_tile(dst, phL + (size_t)t * 128 * 256, 256);
        else             load_tile(dst, gvb + t * 128, NDIM);
    };

    // prologue
    load_tile(smem + 4u * 32768u, thH, 256);   // thetaH temp
    load_tile(THL, thL, 256);                  // thetaL temp
    issue_item(0); issue_item(1); issue_item(2); issue_item(3);

    const uint32_t aOff = (uint32_t)((wid * 16 + (lane & 15)) * 128 + (lane >> 4) * 16);
    const uint32_t bOff = (uint32_t)((((lane & 7) + ((lane >> 4) << 3)) * 128) + ((lane >> 3) & 1) * 16);

    // preload theta hi/lo fragments (iteration-invariant)
    asm volatile("cp.async.wait_group 4;" ::: "memory");
    __syncthreads();
    uint32_t tH[8][4], tL[8][4];
#pragma unroll
    for (int q = 0; q < 8; q++) {
        const uint32_t so = (uint32_t)(q >> 2) * 16384, ko = (uint32_t)(q & 3) * 32;
        LDSM_X4(tH[q], smem + 4u * 32768u + so + swz(aOff + ko));
        LDSM_X4(tL[q], THL + so + swz(aOff + ko));
    }
    __syncthreads();
    issue_item(4);

    float O[16][4];
#pragma unroll
    for (int nj = 0; nj < 16; nj++) { O[nj][0] = O[nj][1] = O[nj][2] = O[nj][3] = 0.f; }
    float rs0 = 0.f, rs1 = 0.f, mx0 = -1e30f, mx1 = -1e30f;

    for (int t = 0; t < 32; t++) {
        float S[16][4];
#pragma unroll
        for (int nj = 0; nj < 16; nj++) { S[nj][0] = S[nj][1] = S[nj][2] = S[nj][3] = 0.f; }
        uint32_t* Sp = reinterpret_cast<uint32_t*>(&S[0][0]);
        const int i0 = 3 * t;

        // ---- stage 0 (phiH): S += thH*phiH + thL*phiH
        asm volatile("cp.async.wait_group 4;" ::: "memory");
        __syncthreads();
        {
            const uint32_t B0 = smem + (uint32_t)(i0 % 5) * 32768u;
#pragma unroll
            for (int q = 0; q < 8; q++) {
                const uint32_t so = (uint32_t)(q >> 2) * 16384, ko = (uint32_t)(q & 3) * 32;
#pragma unroll
                for (int p = 0; p < 8; p++) {
                    uint32_t bb[4];
                    LDSM_X4(bb, B0 + so + swz(bOff + (uint32_t)p * 2048 + ko));
                    MMAF16(S[2 * p],     tH[q], bb[0], bb[1]);
                    MMAF16(S[2 * p + 1], tH[q], bb[2], bb[3]);
                    MMAF16(S[2 * p],     tL[q], bb[0], bb[1]);
                    MMAF16(S[2 * p + 1], tL[q], bb[2], bb[3]);
                }
            }
        }
        __syncthreads();
        if (i0 + 5 < 96) issue_item(i0 + 5); else CP_COMMIT();

        // ---- stage 1 (phiL): S += thH*phiL
        asm volatile("cp.async.wait_group 4;" ::: "memory");
        __syncthreads();
        {
            const uint32_t B1 = smem + (uint32_t)((i0 + 1) % 5) * 32768u;
#pragma unroll
            for (int q = 0; q < 8; q++) {
                const uint32_t so = (uint32_t)(q >> 2) * 16384, ko = (uint32_t)(q & 3) * 32;
#pragma unroll
                for (int p = 0; p < 8; p++) {
                    uint32_t bb[4];
                    LDSM_X4(bb, B1 + so + swz(bOff + (uint32_t)p * 2048 + ko));
                    MMAF16(S[2 * p],     tH[q], bb[0], bb[1]);
                    MMAF16(S[2 * p + 1], tH[q], bb[2], bb[3]);
                }
            }
        }
        __syncthreads();
        if (i0 + 6 < 96) issue_item(i0 + 6); else CP_COMMIT();

        // ---- convert: running-max rescale, P = 2^(S-mx) fp16 (packed in place)
        float cm0 = -1e30f, cm1 = -1e30f;
#pragma unroll
        for (int nj = 0; nj < 16; nj++) {
            cm0 = fmaxf(cm0, fmaxf(S[nj][0], S[nj][1]));
            cm1 = fmaxf(cm1, fmaxf(S[nj][2], S[nj][3]));
        }
        cm0 = fmaxf(cm0, __shfl_xor_sync(0xFFFFFFFFu, cm0, 1));
        cm0 = fmaxf(cm0, __shfl_xor_sync(0xFFFFFFFFu, cm0, 2));
        cm1 = fmaxf(cm1, __shfl_xor_sync(0xFFFFFFFFu, cm1, 1));
        cm1 = fmaxf(cm1, __shfl_xor_sync(0xFFFFFFFFu, cm1, 2));
        const float nm0 = fmaxf(mx0, cm0), nm1 = fmaxf(mx1, cm1);
        const float f0 = ex2(mx0 - nm0), f1 = ex2(mx1 - nm1);
        mx0 = nm0; mx1 = nm1;
        rs0 *= f0; rs1 *= f1;
#pragma unroll
        for (int nj = 0; nj < 16; nj++) {
            O[nj][0] *= f0; O[nj][1] *= f0; O[nj][2] *= f1; O[nj][3] *= f1;
        }
#pragma unroll
        for (int nj = 0; nj < 16; nj++) {
            float e0 = ex2(S[nj][0] - mx0), e1 = ex2(S[nj][1] - mx0);
            float e2 = ex2(S[nj][2] - mx1), e3 = ex2(S[nj][3] - mx1);
            rs0 += e0 + e1; rs1 += e2 + e3;
            __half2 p0 = __floats2half2_rn(e0, e1);
            __half2 p1 = __floats2half2_rn(e2, e3);
            Sp[2 * nj]     = *(uint32_t*)&p0;
            Sp[2 * nj + 1] = *(uint32_t*)&p1;
        }

        // ---- stage 2 (g): O += P*g
        asm volatile("cp.async.wait_group 4;" ::: "memory");
        __syncthreads();
        {
            const uint32_t B2 = smem + (uint32_t)((i0 + 2) % 5) * 32768u;
#pragma unroll
            for (int q = 0; q < 8; q++) {
                const uint32_t so = (uint32_t)(q >> 2) * 16384, ko = (uint32_t)(q & 3) * 32;
                uint32_t aP[4] = { Sp[4 * q], Sp[4 * q + 1], Sp[4 * q + 2], Sp[4 * q + 3] };
#pragma unroll
                for (int p = 0; p < 8; p++) {
                    uint32_t bb[4];
                    LDSM_X4(bb, B2 + so + swz(bOff + (uint32_t)p * 2048 + ko));
                    MMAF16(O[2 * p],     aP, bb[0], bb[1]);
                    MMAF16(O[2 * p + 1], aP, bb[2], bb[3]);
                }
            }
        }
        __syncthreads();
        if (i0 + 7 < 96) issue_item(i0 + 7); else CP_COMMIT();
    }

    // ================= fused final projection =================
    load_tile(smem + 0u,      OW, CIDIM);
    load_tile(smem + 32768u,  OW + 128 * CIDIM, CIDIM);

    rs0 += __shfl_xor_sync(0xFFFFFFFFu, rs0, 1);
    rs0 += __shfl_xor_sync(0xFFFFFFFFu, rs0, 2);
    rs1 += __shfl_xor_sync(0xFFFFFFFFu, rs1, 1);
    rs1 += __shfl_xor_sync(0xFFFFFFFFu, rs1, 2);
    const float inv0 = 1.f / rs0, inv1 = 1.f / rs1;

    // write normalized mid (fp16) into slot 2: tile [n-local 128][ci 128]
    char* dbase = (char*)(((uintptr_t)dsm + 1023u) & ~(uintptr_t)1023u);
    {
        const int rloc = wid * 16 + (lane >> 2);
#pragma unroll
        for (int nj = 0; nj < 16; nj++) {
            const int col = nj * 8 + (lane & 3) * 2;
            const uint32_t sub = (uint32_t)(col >> 6) * 16384u;
            const uint32_t cb  = (uint32_t)(col & 63) * 2u;
            __half2 v0 = __floats2half2_rn(O[nj][0] * inv0, O[nj][1] * inv0);
            __half2 v1 = __floats2half2_rn(O[nj][2] * inv1, O[nj][3] * inv1);
            *(__half2*)(dbase + 2u * 32768u + sub + swz((uint32_t)rloc * 128u + cb))       = v0;
            *(__half2*)(dbase + 2u * 32768u + sub + swz((uint32_t)(rloc + 8) * 128u + cb)) = v1;
        }
    }
    asm volatile("cp.async.wait_group 0;" ::: "memory");
    __syncthreads();

    // mini-GEMM: out[c][n] = OW[c,:].mid[n,:]  (K=128, single fp16 pass)
    const int wm2 = wid >> 2;
    const int wn2 = wid & 3;
    const uint32_t aOff2 = (uint32_t)((wm2 * 64 + (lane & 15)) * 128 + (lane >> 4) * 16);
    const uint32_t bOff2 = (uint32_t)(((wn2 * 32 + (lane & 7) + ((lane >> 4) << 3)) * 128) + ((lane >> 3) & 1) * 16);
    const uint32_t MID = smem + 2u * 32768u;

#pragma unroll
    for (int ch = 0; ch < 2; ch++) {
        float acc[4][4][4];
#pragma unroll
        for (int i = 0; i < 4; i++)
#pragma unroll
            for (int j = 0; j < 4; j++)
#pragma unroll
                for (int r = 0; r < 4; r++) acc[i][j][r] = 0.f;
        const uint32_t OWb = smem + (uint32_t)ch * 32768u;
#pragma unroll
        for (int q = 0; q < 8; q++) {
            const uint32_t so = (uint32_t)(q >> 2) * 16384, ko = (uint32_t)(q & 3) * 32;
            uint32_t a[4][4];
#pragma unroll
            for (int mi = 0; mi < 4; mi++)
                LDSM_X4(a[mi], OWb + so + swz(aOff2 + (uint32_t)mi * 2048u + ko));
            uint32_t bf[2][4];
#pragma unroll
            for (int njp = 0; njp < 2; njp++)
                LDSM_X4(bf[njp], MID + so + swz(bOff2 + (uint32_t)njp * 2048u + ko));
#pragma unroll
            for (int mi = 0; mi < 4; mi++)
#pragma unroll
                for (int nj = 0; nj < 4; nj++)
                    MMAF16(acc[mi][nj], a[mi], bf[nj >> 1][(nj & 1) * 2], bf[nj >> 1][(nj & 1) * 2 + 1]);
        }
        const int cb0 = ch * 128 + wm2 * 64 + (lane >> 2);
        const int nb2 = n0 + wn2 * 32 + (lane & 3) * 2;
#pragma unroll
        for (int mi = 0; mi < 4; mi++) {
#pragma unroll
            for (int half = 0; half < 2; half++) {
                const int c = cb0 + mi * 16 + half * 8;
                const float bv = out_b[c];
#pragma unroll
                for (int nj = 0; nj < 4; nj++) {
                    const int n = nb2 + nj * 8;
                    const size_t addr = (size_t)b * sX + (size_t)c * NDIM + n;
                    float2 xv = *(const float2*)&x[addr];
                    float2 f;
                    f.x = acc[mi][nj][half * 2 + 0] + bv + xv.x;
                    f.y = acc[mi][nj][half * 2 + 1] + bv + xv.y;
                    *(float2*)&out[addr] = f;
                }
            }
        }
    }
}

// ---------------- prep kernels ----------------
__global__ void split4_k(const float* __restrict__ tw, const float* __restrict__ pw,
                         const float* __restrict__ gw, const float* __restrict__ ow,
                         __half* __restrict__ Wh, __half* __restrict__ Wl,
                         __half* __restrict__ OWs)
{
    const int i = blockIdx.x * 256 + threadIdx.x;
    const int seg = i >> 15, loc = i & 32767;
    if (seg < 3) {
        const float* s = (seg == 0) ? tw : (seg == 1) ? pw : gw;
        __half hh, ll;
        split_f16(s[loc], hh, ll);
        Wh[seg * 32768 + loc] = hh;
        Wl[seg * 32768 + loc] = ll;
    } else {
        OWs[loc] = __float2half_rn(ow[loc]);
    }
}

__global__ void xT_split_k(const float* __restrict__ x,
                           __half* __restrict__ th, __half* __restrict__ tl)
{
    __shared__ float t[32][33];
    const int b = blockIdx.z;
    const int n0 = blockIdx.x * 32, c0 = blockIdx.y * 32;
    const int tx = threadIdx.x, ty = threadIdx.y;
    const float* xb = x + (size_t)b * CDIM * NDIM;
#pragma unroll
    for (int i = 0; i < 32; i += 8)
        t[ty + i][tx] = xb[(size_t)(c0 + ty + i) * NDIM + n0 + tx];
    __syncthreads();
    __half* oh = th + (size_t)b * NDIM * CDIM;
    __half* ol = tl + (size_t)b * NDIM * CDIM;
#pragma unroll
    for (int i = 0; i < 32; i += 8) {
        __half h, l;
        split_f16(t[tx][ty + i], h, l);
        size_t a = (size_t)(n0 + ty + i) * CDIM + c0 + tx;
        oh[a] = h; ol[a] = l;
    }
}

// ---------------- launch ----------------
extern "C" void kernel_launch(void* const* d_in, const int* in_sizes, int n_in,
                              void* d_out, int out_size)
{
    const float* x       = (const float*)d_in[0];
    const float* theta_w = (const float*)d_in[1];
    const float* theta_b = (const float*)d_in[2];
    const float* phi_w   = (const float*)d_in[3];
    const float* phi_b   = (const float*)d_in[4];
    const float* g_w     = (const float*)d_in[5];
    const float* g_b     = (const float*)d_in[6];
    const float* out_w   = (const float*)d_in[7];
    const float* out_b   = (const float*)d_in[8];
    float* out = (float*)d_out;

    __half *xTh, *xTl, *Wh, *Wl, *OWs, *tpH, *tpL, *gv;
    cudaGetSymbolAddress((void**)&xTh, g_xT_h);   cudaGetSymbolAddress((void**)&xTl, g_xT_l);
    cudaGetSymbolAddress((void**)&Wh,  g_W_h);    cudaGetSymbolAddress((void**)&Wl,  g_W_l);
    cudaGetSymbolAddress((void**)&OWs, g_OW);
    cudaGetSymbolAddress((void**)&tpH, g_thph_h); cudaGetSymbolAddress((void**)&tpL, g_thph_l);
    cudaGetSymbolAddress((void**)&gv,  g_gv);

    const int SM  = 1024 + 2 * 32768;      // proj_k: 66560
    const int SMF = 1024 + 6 * 32768;      // fused: 5-slot ring + thetaL staging
    cudaFuncSetAttribute(proj_k, cudaFuncAttributeMaxDynamicSharedMemorySize, SM);
    cudaFuncSetAttribute(fused_attn, cudaFuncAttributeMaxDynamicSharedMemorySize, SMF);

    // prep
    split4_k<<<512, 256>>>(theta_w, phi_w, g_w, out_w, Wh, Wl, OWs);
    xT_split_k<<<dim3(NDIM / 32, CDIM / 32, BATCH), dim3(32, 8)>>>(x, xTh, xTl);

    // 1) merged projections: theta|phi (x=0,1) and g (x=2), one launch
    proj_k<<<dim3(3, 32, BATCH), 256, SM>>>(
        xTh, xTl, Wh, Wl, theta_b, phi_b, g_b, tpH, tpL, gv);

    // 2) fused attention + final projection -> out
    fused_attn<<<dim3(NDIM / 128, BATCH), 256, SMF>>>(
        tpH, tpL, gv, OWs, out_b, x, out);
}